// round 11
// baseline (speedup 1.0000x reference)
#include <cuda_runtime.h>
#include <cuda_bf16.h>

// Bicubic x4 upsample, Keys a=-0.5, matching jax.image.resize(method="cubic").
//   input (16,3,256,256) f32 -> output (16,3,1024,1024) f32
// 256-bit store variant: block = 256 threads, tile = 64x16 input cells
// (256x64 output). Thread (qp, ys) owns x-cell pair {2qp, 2qp+1} and 2 y-cells;
// two rolling 5-deep float4 h-windows; each output row written with ONE
// st.global.cs.v8.f32 (STG.E.256, 32B aligned).
// Borders use masked+renormalized weights (exact jax semantics).

#define IN_W   256
#define IN_H   256
#define OUT_W  1024
#define PLANE_IN  (IN_W * IN_H)
#define PLANE_OUT (OUT_W * OUT_W)

#define A0 (-0.0439453125f)
#define A1 ( 0.3896484375f)
#define A2 ( 0.7275390625f)
#define A3 (-0.0732421875f)
#define B0 (-0.0068359375f)
#define B1 ( 0.0908203125f)
#define B2 ( 0.9638671875f)
#define B3 (-0.0478515625f)

// streaming (evict-first) 256-bit store
__device__ __forceinline__ void stcs8(float* p, float4 a, float4 b) {
    asm volatile("st.global.cs.v8.f32 [%0], {%1,%2,%3,%4,%5,%6,%7,%8};"
                 :: "l"(p),
                    "f"(a.x), "f"(a.y), "f"(a.z), "f"(a.w),
                    "f"(b.x), "f"(b.y), "f"(b.z), "f"(b.w) : "memory");
}

__device__ __forceinline__ float border_dot5(int q, const float wt[5],
                                             float v0, float v1, float v2,
                                             float v3, float v4)
{
    float w[5]; float s = 0.f;
#pragma unroll
    for (int j = 0; j < 5; j++) {
        int idx = q - 2 + j;
        float ww = (idx >= 0 && idx < IN_W) ? wt[j] : 0.f;
        w[j] = ww; s += ww;
    }
    float inv = 1.0f / s;
    float r = w[0] * v0;
    r = fmaf(w[1], v1, r);
    r = fmaf(w[2], v2, r);
    r = fmaf(w[3], v3, r);
    r = fmaf(w[4], v4, r);
    return r * inv;
}

// horizontal 4-phase filter for one cell (interior fast path or border)
__device__ __forceinline__ float4 h_filter(int qg, bool xint,
                                           float v0, float v1, float v2,
                                           float v3, float v4)
{
    float4 h;
    if (xint) {
        h.x = fmaf(A0, v0, fmaf(A1, v1, fmaf(A2, v2, A3 * v3)));
        h.y = fmaf(B0, v0, fmaf(B1, v1, fmaf(B2, v2, B3 * v3)));
        h.z = fmaf(B3, v1, fmaf(B2, v2, fmaf(B1, v3, B0 * v4)));
        h.w = fmaf(A3, v1, fmaf(A2, v2, fmaf(A1, v3, A0 * v4)));
    } else {
        const float TA[5]  = {A0,  A1,  A2,  A3,  0.f};
        const float TB[5]  = {B0,  B1,  B2,  B3,  0.f};
        const float TBr[5] = {0.f, B3,  B2,  B1,  B0 };
        const float TAr[5] = {0.f, A3,  A2,  A1,  A0 };
        h.x = border_dot5(qg, TA,  v0, v1, v2, v3, v4);
        h.y = border_dot5(qg, TB,  v0, v1, v2, v3, v4);
        h.z = border_dot5(qg, TBr, v0, v1, v2, v3, v4);
        h.w = border_dot5(qg, TAr, v0, v1, v2, v3, v4);
    }
    return h;
}

// vertical phase with explicit 5 weights applied to a float4 window
__device__ __forceinline__ float4 vphase(float w0, float w1, float w2, float w3, float w4,
                                         float4 v0, float4 v1, float4 v2, float4 v3, float4 v4)
{
    float4 o;
    o.x = fmaf(w4, v4.x, fmaf(w3, v3.x, fmaf(w2, v2.x, fmaf(w1, v1.x, w0 * v0.x))));
    o.y = fmaf(w4, v4.y, fmaf(w3, v3.y, fmaf(w2, v2.y, fmaf(w1, v1.y, w0 * v0.y))));
    o.z = fmaf(w4, v4.z, fmaf(w3, v3.z, fmaf(w2, v2.z, fmaf(w1, v1.z, w0 * v0.z))));
    o.w = fmaf(w4, v4.w, fmaf(w3, v3.w, fmaf(w2, v2.w, fmaf(w1, v1.w, w0 * v0.w))));
    return o;
}

__global__ void __launch_bounds__(256, 4)
bicubic4x_v8_kernel(const float* __restrict__ in, float* __restrict__ out)
{
    __shared__ float sin_t[20][72];    // 20x68 halo, padded rows (5.76 KB)

    const int tid   = threadIdx.x;
    const int qx0   = blockIdx.x * 64;     // tile origin (x cells)
    const int qy0   = blockIdx.y * 16;     // tile origin (y cells)
    const int plane = blockIdx.z;

    const bool xedge = (blockIdx.x == 0) | (blockIdx.x == 3);
    const bool yedge = (blockIdx.y == 0) | (blockIdx.y == 15);

    const float* ip = in + (size_t)plane * PLANE_IN;

    // ---------- Phase A: stage 20x68 halo (coalesced, clamped) ----------
#pragma unroll
    for (int i = tid; i < 20 * 68; i += 256) {
        int r = i / 68;
        int c = i - r * 68;
        int gy = qy0 - 2 + r;  gy = gy < 0 ? 0 : (gy > IN_H - 1 ? IN_H - 1 : gy);
        int gx = qx0 - 2 + c;  gx = gx < 0 ? 0 : (gx > IN_W - 1 ? IN_W - 1 : gx);
        sin_t[r][c] = __ldg(ip + gy * IN_W + gx);
    }
    __syncthreads();

    // ---------- Fused pass ----------
    // Thread (qp, ys): x-cells 2qp, 2qp+1 (local), y-cells ys*2, ys*2+1.
    const int qp  = tid & 31;            // x-pair index 0..31
    const int ys  = tid >> 5;            // 0..7
    const int xl  = qp * 2;              // local first x cell
    const int qgL = qx0 + xl;            // global x cells
    const int qgR = qgL + 1;
    const int rb  = ys * 2;              // first halo row of this strip
    const bool xintL = !xedge || (qgL >= 2 && qgL <= IN_W - 3);
    const bool xintR = !xedge || (qgR >= 2 && qgR <= IN_W - 3);

    // compute h pair for halo row rr: 6 scalar taps -> two float4 phases
#define COMPUTE_H2(dL, dR, rr)                                                  \
    {                                                                           \
        const float* srow = sin_t[rr];                                          \
        float u0 = srow[xl + 0], u1 = srow[xl + 1], u2 = srow[xl + 2],          \
              u3 = srow[xl + 3], u4 = srow[xl + 4], u5 = srow[xl + 5];          \
        dL = h_filter(qgL, xintL, u0, u1, u2, u3, u4);                          \
        dR = h_filter(qgR, xintR, u1, u2, u3, u4, u5);                          \
    }

    float4 l0, l1, l2, l3, l4;   // left-cell window
    float4 r0, r1, r2, r3, r4;   // right-cell window
    COMPUTE_H2(l0, r0, rb + 0);
    COMPUTE_H2(l1, r1, rb + 1);
    COMPUTE_H2(l2, r2, rb + 2);
    COMPUTE_H2(l3, r3, rb + 3);
    COMPUTE_H2(l4, r4, rb + 4);

    // output base: row 4*(qy0+rb), column 4*qx0 + 8*qp  (32B aligned)
    float* op0 = out + (size_t)plane * PLANE_OUT
                     + (size_t)((qy0 + rb) * 4) * OUT_W
                     + (size_t)(qx0 * 4) + (size_t)qp * 8;

    static const float TA[5]  = {A0,  A1,  A2,  A3,  0.f};
    static const float TB[5]  = {B0,  B1,  B2,  B3,  0.f};
    static const float TBr[5] = {0.f, B3,  B2,  B1,  B0 };
    static const float TAr[5] = {0.f, A3,  A2,  A1,  A0 };

#pragma unroll
    for (int c = 0; c < 2; c++) {
        const int qyg = qy0 + rb + c;
        float* op = op0 + (size_t)(c * 4) * OUT_W;

        if (!yedge || (qyg >= 2 && qyg <= IN_H - 3)) {
            stcs8(op,
                  vphase(A0, A1, A2, A3, 0.f, l0, l1, l2, l3, l4),
                  vphase(A0, A1, A2, A3, 0.f, r0, r1, r2, r3, r4));
            stcs8(op + OUT_W,
                  vphase(B0, B1, B2, B3, 0.f, l0, l1, l2, l3, l4),
                  vphase(B0, B1, B2, B3, 0.f, r0, r1, r2, r3, r4));
            stcs8(op + 2 * OUT_W,
                  vphase(0.f, B3, B2, B1, B0, l0, l1, l2, l3, l4),
                  vphase(0.f, B3, B2, B1, B0, r0, r1, r2, r3, r4));
            stcs8(op + 3 * OUT_W,
                  vphase(0.f, A3, A2, A1, A0, l0, l1, l2, l3, l4),
                  vphase(0.f, A3, A2, A1, A0, r0, r1, r2, r3, r4));
        } else {
            // border rows: masked + renormalized vertical weights
            const float* tabs[4] = {TA, TB, TBr, TAr};
#pragma unroll
            for (int p = 0; p < 4; p++) {
                float w[5]; float s = 0.f;
#pragma unroll
                for (int j = 0; j < 5; j++) {
                    int idx = qyg - 2 + j;
                    float ww = (idx >= 0 && idx < IN_H) ? tabs[p][j] : 0.f;
                    w[j] = ww; s += ww;
                }
                float inv = 1.0f / s;
                float4 oL = vphase(w[0], w[1], w[2], w[3], w[4], l0, l1, l2, l3, l4);
                float4 oR = vphase(w[0], w[1], w[2], w[3], w[4], r0, r1, r2, r3, r4);
                oL.x *= inv; oL.y *= inv; oL.z *= inv; oL.w *= inv;
                oR.x *= inv; oR.y *= inv; oR.z *= inv; oR.w *= inv;
                stcs8(op + (size_t)p * OUT_W, oL, oR);
            }
        }

        if (c < 1) {                      // roll both windows once
            l0 = l1; l1 = l2; l2 = l3; l3 = l4;
            r0 = r1; r1 = r2; r2 = r3; r3 = r4;
            COMPUTE_H2(l4, r4, rb + 5);
        }
    }
#undef COMPUTE_H2
}

extern "C" void kernel_launch(void* const* d_in, const int* in_sizes, int n_in,
                              void* d_out, int out_size)
{
    const float* x   = (const float*)d_in[0];
    float*       out = (float*)d_out;

    dim3 grid(4, 16, 48);   // 4x16 tiles per plane, 48 planes = 3072 blocks
    bicubic4x_v8_kernel<<<grid, 256>>>(x, out);
}

// round 12
// speedup vs baseline: 1.3138x; 1.3138x over previous
#include <cuda_runtime.h>
#include <cuda_bf16.h>

// Bicubic x4 upsample, Keys a=-0.5, matching jax.image.resize(method="cubic").
//   input (16,3,256,256) f32 -> output (16,3,1024,1024) f32
// Block = 256 threads, 32x32 input cells -> 128x128 output tile.
//   Phase A: stage 36x36 input halo in smem (coalesced, clamped)
//   Fused:   each thread owns one x-cell column and 4 y-cells; rolling 5-deep
//            float4 h-window in registers; streaming float4 stores (evict-first).
// Borders (edge blocks only) use masked+renormalized weights (jax semantics).
//
// FINAL KERNEL (R7 configuration, best bench 34.8us).
// Experiment ledger: R6 fusion (neutral), R8 finer tiles (neutral), R9
// full-row write tiles (neutral), R11 256-bit stores (regression) — all
// confirm this kernel sits on the HBM write-stream drain floor (~33-35us
// for the 192MB output); .cs streaming 128-bit stores + 6 CTAs/SM is the
// optimal configuration found.

#define IN_W   256
#define IN_H   256
#define OUT_W  1024
#define PLANE_IN  (IN_W * IN_H)
#define PLANE_OUT (OUT_W * OUT_W)

#define A0 (-0.0439453125f)
#define A1 ( 0.3896484375f)
#define A2 ( 0.7275390625f)
#define A3 (-0.0732421875f)
#define B0 (-0.0068359375f)
#define B1 ( 0.0908203125f)
#define B2 ( 0.9638671875f)
#define B3 (-0.0478515625f)

// streaming (evict-first) 128-bit store
__device__ __forceinline__ void stcs4(float* p, float4 v) {
    asm volatile("st.global.cs.v4.f32 [%0], {%1,%2,%3,%4};"
                 :: "l"(p), "f"(v.x), "f"(v.y), "f"(v.z), "f"(v.w) : "memory");
}

__device__ __forceinline__ float border_dot5(int q, const float wt[5],
                                             float v0, float v1, float v2,
                                             float v3, float v4)
{
    float w[5]; float s = 0.f;
#pragma unroll
    for (int j = 0; j < 5; j++) {
        int idx = q - 2 + j;
        float ww = (idx >= 0 && idx < IN_W) ? wt[j] : 0.f;
        w[j] = ww; s += ww;
    }
    float inv = 1.0f / s;
    float r = w[0] * v0;
    r = fmaf(w[1], v1, r);
    r = fmaf(w[2], v2, r);
    r = fmaf(w[3], v3, r);
    r = fmaf(w[4], v4, r);
    return r * inv;
}

__device__ __forceinline__ float4 border_dot5_v4(int q, const float wt[5],
                                                 float4 v0, float4 v1, float4 v2,
                                                 float4 v3, float4 v4)
{
    float w[5]; float s = 0.f;
#pragma unroll
    for (int j = 0; j < 5; j++) {
        int idx = q - 2 + j;
        float ww = (idx >= 0 && idx < IN_H) ? wt[j] : 0.f;
        w[j] = ww; s += ww;
    }
    float inv = 1.0f / s;
    float4 o;
    o.x = (fmaf(w[4], v4.x, fmaf(w[3], v3.x, fmaf(w[2], v2.x, fmaf(w[1], v1.x, w[0] * v0.x))))) * inv;
    o.y = (fmaf(w[4], v4.y, fmaf(w[3], v3.y, fmaf(w[2], v2.y, fmaf(w[1], v1.y, w[0] * v0.y))))) * inv;
    o.z = (fmaf(w[4], v4.z, fmaf(w[3], v3.z, fmaf(w[2], v2.z, fmaf(w[1], v1.z, w[0] * v0.z))))) * inv;
    o.w = (fmaf(w[4], v4.w, fmaf(w[3], v3.w, fmaf(w[2], v2.w, fmaf(w[1], v1.w, w[0] * v0.w))))) * inv;
    return o;
}

__global__ void __launch_bounds__(256, 6)
bicubic4x_fused6_kernel(const float* __restrict__ in, float* __restrict__ out)
{
    __shared__ float sin_t[36][40];    // input halo only (5.76 KB)

    const int tid   = threadIdx.x;
    const int qx0   = blockIdx.x * 32;
    const int qy0   = blockIdx.y * 32;
    const int plane = blockIdx.z;

    const bool xedge = (blockIdx.x == 0) | (blockIdx.x == 7);
    const bool yedge = (blockIdx.y == 0) | (blockIdx.y == 7);

    const float* ip = in + (size_t)plane * PLANE_IN;

    static const float TA[5]  = {A0,  A1,  A2,  A3,  0.f};
    static const float TB[5]  = {B0,  B1,  B2,  B3,  0.f};
    static const float TBr[5] = {0.f, B3,  B2,  B1,  B0 };
    static const float TAr[5] = {0.f, A3,  A2,  A1,  A0 };

    // ---------- Phase A: stage 36x36 halo (coalesced, clamped) ----------
#pragma unroll
    for (int i = tid; i < 36 * 36; i += 256) {
        int r = i / 36;
        int c = i - r * 36;
        int gy = qy0 - 2 + r;  gy = gy < 0 ? 0 : (gy > IN_H - 1 ? IN_H - 1 : gy);
        int gx = qx0 - 2 + c;  gx = gx < 0 ? 0 : (gx > IN_W - 1 ? IN_W - 1 : gx);
        sin_t[r][c] = __ldg(ip + gy * IN_W + gx);
    }
    __syncthreads();

    // ---------- Fused horizontal + vertical pass ----------
    const int q   = tid & 31;
    const int ys  = tid >> 5;            // 0..7
    const int qg  = qx0 + q;             // global x cell
    const int rb  = ys * 4;              // first halo row of this strip
    const bool xint = !xedge || (qg >= 2 && qg <= IN_W - 3);

#define COMPUTE_H(dst, rr)                                                      \
    {                                                                           \
        const float* srow = sin_t[rr];                                          \
        float v0 = srow[q + 0], v1 = srow[q + 1], v2 = srow[q + 2],             \
              v3 = srow[q + 3], v4 = srow[q + 4];                               \
        if (xint) {                                                             \
            dst.x = fmaf(A0, v0, fmaf(A1, v1, fmaf(A2, v2, A3 * v3)));          \
            dst.y = fmaf(B0, v0, fmaf(B1, v1, fmaf(B2, v2, B3 * v3)));          \
            dst.z = fmaf(B3, v1, fmaf(B2, v2, fmaf(B1, v3, B0 * v4)));          \
            dst.w = fmaf(A3, v1, fmaf(A2, v2, fmaf(A1, v3, A0 * v4)));          \
        } else {                                                                \
            dst.x = border_dot5(qg, TA,  v0, v1, v2, v3, v4);                   \
            dst.y = border_dot5(qg, TB,  v0, v1, v2, v3, v4);                   \
            dst.z = border_dot5(qg, TBr, v0, v1, v2, v3, v4);                   \
            dst.w = border_dot5(qg, TAr, v0, v1, v2, v3, v4);                   \
        }                                                                       \
    }

    float4 h0, h1, h2, h3, h4;
    COMPUTE_H(h0, rb + 0);
    COMPUTE_H(h1, rb + 1);
    COMPUTE_H(h2, rb + 2);
    COMPUTE_H(h3, rb + 3);
    COMPUTE_H(h4, rb + 4);

    // base output pointer for this thread's first output row
    float* op0 = out + (size_t)plane * PLANE_OUT
                     + (size_t)((qy0 + rb) * 4) * OUT_W
                     + (size_t)(qx0 * 4) + (size_t)q * 4;

#pragma unroll
    for (int c = 0; c < 4; c++) {
        const int qyg = qy0 + rb + c;
        float* op = op0 + (size_t)(c * 4) * OUT_W;

        if (!yedge || (qyg >= 2 && qyg <= IN_H - 3)) {
            float4 o;
            o.x = fmaf(A0, h0.x, fmaf(A1, h1.x, fmaf(A2, h2.x, A3 * h3.x)));
            o.y = fmaf(A0, h0.y, fmaf(A1, h1.y, fmaf(A2, h2.y, A3 * h3.y)));
            o.z = fmaf(A0, h0.z, fmaf(A1, h1.z, fmaf(A2, h2.z, A3 * h3.z)));
            o.w = fmaf(A0, h0.w, fmaf(A1, h1.w, fmaf(A2, h2.w, A3 * h3.w)));
            stcs4(op, o);

            o.x = fmaf(B0, h0.x, fmaf(B1, h1.x, fmaf(B2, h2.x, B3 * h3.x)));
            o.y = fmaf(B0, h0.y, fmaf(B1, h1.y, fmaf(B2, h2.y, B3 * h3.y)));
            o.z = fmaf(B0, h0.z, fmaf(B1, h1.z, fmaf(B2, h2.z, B3 * h3.z)));
            o.w = fmaf(B0, h0.w, fmaf(B1, h1.w, fmaf(B2, h2.w, B3 * h3.w)));
            stcs4(op + OUT_W, o);

            o.x = fmaf(B3, h1.x, fmaf(B2, h2.x, fmaf(B1, h3.x, B0 * h4.x)));
            o.y = fmaf(B3, h1.y, fmaf(B2, h2.y, fmaf(B1, h3.y, B0 * h4.y)));
            o.z = fmaf(B3, h1.z, fmaf(B2, h2.z, fmaf(B1, h3.z, B0 * h4.z)));
            o.w = fmaf(B3, h1.w, fmaf(B2, h2.w, fmaf(B1, h3.w, B0 * h4.w)));
            stcs4(op + 2 * OUT_W, o);

            o.x = fmaf(A3, h1.x, fmaf(A2, h2.x, fmaf(A1, h3.x, A0 * h4.x)));
            o.y = fmaf(A3, h1.y, fmaf(A2, h2.y, fmaf(A1, h3.y, A0 * h4.y)));
            o.z = fmaf(A3, h1.z, fmaf(A2, h2.z, fmaf(A1, h3.z, A0 * h4.z)));
            o.w = fmaf(A3, h1.w, fmaf(A2, h2.w, fmaf(A1, h3.w, A0 * h4.w)));
            stcs4(op + 3 * OUT_W, o);
        } else {
            stcs4(op,             border_dot5_v4(qyg, TA,  h0, h1, h2, h3, h4));
            stcs4(op + OUT_W,     border_dot5_v4(qyg, TB,  h0, h1, h2, h3, h4));
            stcs4(op + 2 * OUT_W, border_dot5_v4(qyg, TBr, h0, h1, h2, h3, h4));
            stcs4(op + 3 * OUT_W, border_dot5_v4(qyg, TAr, h0, h1, h2, h3, h4));
        }

        if (c < 3) {                      // roll the h window
            h0 = h1; h1 = h2; h2 = h3; h3 = h4;
            COMPUTE_H(h4, rb + c + 5);
        }
    }
#undef COMPUTE_H
}

extern "C" void kernel_launch(void* const* d_in, const int* in_sizes, int n_in,
                              void* d_out, int out_size)
{
    const float* x   = (const float*)d_in[0];
    float*       out = (float*)d_out;

    dim3 grid(8, 8, 48);   // 8x8 tiles per plane, 48 planes
    bicubic4x_fused6_kernel<<<grid, 256>>>(x, out);
}